// round 13
// baseline (speedup 1.0000x reference)
#include <cuda_runtime.h>
#include <cuda_bf16.h>
#include <math.h>
#include <stdint.h>

#define B_ 2048
#define D_ 512
#define C_ 10000
#define CPAD 10112          // 79 * 128
#define NTC 79              // AAM col tiles of 128
#define NQCT 32             // QK col tiles of 64
#define NAAMBLK (NTC * (B_ / 128))        // 1264
#define NQKBLK  (NQCT * (B_ / 128))       // 512
#define NMEGA (NAAMBLK + NQKBLK)          // 1776
#define NFINAL 8

// ---------- scratch (device globals: alloc-free, capture-safe) ----------
__device__ __nv_bfloat16 g_xh[B_ * D_];
__device__ __nv_bfloat16 g_wh[(size_t)CPAD * D_];
__device__ __nv_bfloat16 g_wmh[B_ * D_];
__device__ __nv_bfloat16 g_wkh[B_ * D_];
__device__ float g_rexp[B_];
__device__ float g_rsum[B_];
__device__ float g_nmp[B_];
__device__ float g_cy[B_];
__device__ float g_expneg[B_];
__device__ float g_cos_apm[B_];
__device__ float g_sin_apm[B_];
__device__ float g_acc[3];
__device__ unsigned g_ticket;

// ---------- constants ----------
constexpr float K_S    = 30.0f;
constexpr float K_COSM = 0.9800665778412416f;
constexpr float K_SINM = 0.19866933079506122f;
constexpr float K_TH   = -0.9800665778412416f;
constexpr float K_MM   = 0.039733866159012244f;
constexpr float K_EPS  = 0.1f;
constexpr float K_L2E  = 1.4426950408889634f;
constexpr float K_LN2  = 0.6931471805599453f;

// ---------- fast math (MUFU) ----------
__device__ __forceinline__ float exp_approx(float x) {
    float r;
    asm("ex2.approx.f32 %0, %1;" : "=f"(r) : "f"(x * K_L2E));
    return r;
}
__device__ __forceinline__ float log_approx(float x) {
    float r;
    asm("lg2.approx.f32 %0, %1;" : "=f"(r) : "f"(x));
    return r * K_LN2;
}
__device__ __forceinline__ float sqrt_approx(float x) {
    float r;
    asm("sqrt.approx.f32 %0, %1;" : "=f"(r) : "f"(x));
    return r;
}

// ---------- block-wide sum (final_combine only) ----------
__device__ __forceinline__ float block_sum_all(float v) {
    __shared__ float sh[33];
    int lane = threadIdx.x & 31, wid = threadIdx.x >> 5;
#pragma unroll
    for (int o = 16; o; o >>= 1) v += __shfl_down_sync(0xffffffffu, v, o);
    __syncthreads();
    if (lane == 0) sh[wid] = v;
    __syncthreads();
    if (threadIdx.x == 0) {
        float s = 0.f;
        int nw = (blockDim.x + 31) >> 5;
        for (int w = 0; w < nw; w++) s += sh[w];
        sh[32] = s;
    }
    __syncthreads();
    return sh[32];
}

// ---------- warp-per-row L2 normalize -> bf16 (no block barriers) ----------
__device__ __forceinline__ void warp_norm(const float* __restrict__ src,
                                          __nv_bfloat16* __restrict__ dst, int lane) {
    const float4* sp = (const float4*)src + lane * 4;
    float4 v[4];
    float ss = 0.f;
#pragma unroll
    for (int e = 0; e < 4; e++) {
        v[e] = sp[e];
        ss += v[e].x * v[e].x + v[e].y * v[e].y + v[e].z * v[e].z + v[e].w * v[e].w;
    }
#pragma unroll
    for (int o = 16; o; o >>= 1) ss += __shfl_xor_sync(0xffffffffu, ss, o);
    float inv = 1.0f / fmaxf(sqrtf(ss), 1e-12f);
    uint32_t po[8];
#pragma unroll
    for (int e = 0; e < 4; e++) {
        __nv_bfloat162 p0 = __floats2bfloat162_rn(v[e].x * inv, v[e].y * inv);
        __nv_bfloat162 p1 = __floats2bfloat162_rn(v[e].z * inv, v[e].w * inv);
        po[2 * e + 0] = *(uint32_t*)&p0;
        po[2 * e + 1] = *(uint32_t*)&p1;
    }
    uint4* dp = (uint4*)(dst + lane * 16);
    dp[0] = make_uint4(po[0], po[1], po[2], po[3]);
    dp[1] = make_uint4(po[4], po[5], po[6], po[7]);
}

#define NROWS_NORM (CPAD + B_ + B_)
#define NB_NORM (NROWS_NORM / 8)             // 1776
#define NB_ZERO 8
#define PREP_APMB (NB_NORM + NB_ZERO)
#define PREP_GRID (PREP_APMB + B_ / 8)

__global__ void __launch_bounds__(256)
prep_kernel(const float* __restrict__ x, const float* __restrict__ w,
            const float* __restrict__ wm, const float* __restrict__ wk,
            const int* __restrict__ label) {
    int b = blockIdx.x, t = threadIdx.x;
    int wv = t >> 5, lane = t & 31;
    if (b < NB_NORM) {
        int row = b * 8 + wv;
        if (row < CPAD) {
            __nv_bfloat16* dst = g_wh + (size_t)row * D_;
            if (row >= C_) {
                uint4* dp = (uint4*)(dst + lane * 16);
                uint4 z = make_uint4(0u, 0u, 0u, 0u);
                dp[0] = z; dp[1] = z;
            } else {
                warp_norm(w + (size_t)row * D_, dst, lane);
            }
        } else if (row < CPAD + B_) {
            int r = row - CPAD;
            warp_norm(x + (size_t)r * D_, g_xh + (size_t)r * D_, lane);
        } else {
            int i = row - CPAD - B_;
            int c = label[i];
            warp_norm(wm + (size_t)c * D_, g_wmh + (size_t)i * D_, lane);
            warp_norm(wk + (size_t)c * D_, g_wkh + (size_t)i * D_, lane);
        }
    } else if (b < PREP_APMB) {
        int idx = (b - NB_NORM) * 256 + t;
        g_rexp[idx] = 0.f;
        g_rsum[idx] = 0.f;
        g_nmp[idx]  = 0.f;
        if (b == NB_NORM) {
            if (t < 3) g_acc[t] = 0.f;
            if (t == 3) g_ticket = 0u;
        }
    } else {
        // apm: warp per row; ap_m == ap exactly (all matched sim values identical)
        int i = (b - PREP_APMB) * 8 + wv;
        int li = label[i];
        const float4* xp = (const float4*)(x  + (size_t)i  * D_) + lane * 4;
        const float4* qp = (const float4*)(wm + (size_t)li * D_) + lane * 4;
        const float4* kp = (const float4*)(wk + (size_t)li * D_) + lane * 4;
        float xx = 0.f, xq = 0.f, qq = 0.f, xk = 0.f, kk = 0.f;
#pragma unroll
        for (int e = 0; e < 4; e++) {
            float4 xv = xp[e], qv = qp[e], kv = kp[e];
            xx += xv.x * xv.x + xv.y * xv.y + xv.z * xv.z + xv.w * xv.w;
            xq += xv.x * qv.x + xv.y * qv.y + xv.z * qv.z + xv.w * qv.w;
            qq += qv.x * qv.x + qv.y * qv.y + qv.z * qv.z + qv.w * qv.w;
            xk += xv.x * kv.x + xv.y * kv.y + xv.z * kv.z + xv.w * kv.w;
            kk += kv.x * kv.x + kv.y * kv.y + kv.z * kv.z + kv.w * kv.w;
        }
#pragma unroll
        for (int o = 16; o; o >>= 1) {
            xx += __shfl_xor_sync(0xffffffffu, xx, o);
            xq += __shfl_xor_sync(0xffffffffu, xq, o);
            qq += __shfl_xor_sync(0xffffffffu, qq, o);
            xk += __shfl_xor_sync(0xffffffffu, xk, o);
            kk += __shfl_xor_sync(0xffffffffu, kk, o);
        }
        if (lane == 0) {
            float dq = xq / fmaxf(sqrtf(xx * qq), 1e-24f);
            float dk = xk / fmaxf(sqrtf(xx * kk), 1e-24f);
            float ap = dq * dk;
            float ca = fminf(fmaxf(ap, 0.f), 1.f);
            float sa = sqrt_approx(fminf(fmaxf(1.f - ca, 0.f), 1.f));
            g_cos_apm[i] = ca;
            g_sin_apm[i] = sa;
            float pc = ca * ca - sa * sa;
            float ps = sqrt_approx(fminf(fmaxf(1.f - pc, 0.f), 1.f));
            float phi_pm = pc * K_COSM - ps * K_SINM;
            g_expneg[i] = exp_approx(1.f - phi_pm);
        }
    }
}

// ============== mma.sync bf16 building blocks ==============
__device__ __forceinline__ void ldsm4(uint32_t& r0, uint32_t& r1, uint32_t& r2, uint32_t& r3,
                                      uint32_t addr) {
    asm volatile("ldmatrix.sync.aligned.m8n8.x4.shared.b16 {%0,%1,%2,%3},[%4];\n"
                 : "=r"(r0), "=r"(r1), "=r"(r2), "=r"(r3) : "r"(addr));
}
__device__ __forceinline__ void mma16816(float* c, const uint32_t* a, uint32_t b0, uint32_t b1) {
    asm volatile("mma.sync.aligned.m16n8k16.row.col.f32.bf16.bf16.f32 "
                 "{%0,%1,%2,%3},{%4,%5,%6,%7},{%8,%9},{%0,%1,%2,%3};\n"
                 : "+f"(c[0]), "+f"(c[1]), "+f"(c[2]), "+f"(c[3])
                 : "r"(a[0]), "r"(a[1]), "r"(a[2]), "r"(a[3]), "r"(b0), "r"(b1));
}
__device__ __forceinline__ void cpasync16(uint32_t s, const void* g) {
    asm volatile("cp.async.cg.shared.global [%0],[%1],16;\n" :: "r"(s), "l"(g));
}

// K-chunk = 64 cols (128 bytes), row stride padded to 144 B (conflict-free ldmatrix:
// bank stride 36 = 4 mod 32, 8 consecutive rows hit 8 distinct banks)
#define ROWB2 144
#define A_BYTES (128 * ROWB2)        // 18432
#define STG2 (256 * ROWB2)           // 36864 per stage (A:128 + B:128 rows, or A+Bq64+Bk64)
#define NST2 3
#define GEMM_SMEM (NST2 * STG2)      // 110592
#define NIT2 8                       // K=512 / 64

// ---------------- AAM role (128x128 tile) ----------------
struct TileCtx {
    uint32_t aOff[2], bOff[4];
    uint32_t sa, sb;
    const __nv_bfloat16 *pa, *pb;
    int wm, wn, lane;
};

__device__ __forceinline__ void tile_init(TileCtx& T, uint32_t sbase, int tid,
                                          const __nv_bfloat16* A, const __nv_bfloat16* Bm,
                                          int bm, int bn) {
    int lane = tid & 31, warp = tid >> 5;
    T.lane = lane;
    T.wm = warp >> 1; T.wn = warp & 1;
    uint32_t sA0 = sbase, sB0 = sbase + A_BYTES;
    int aRow = T.wm * 32 + (lane & 7) + ((lane >> 3) & 1) * 8;
    int aCol = ((lane >> 4) & 1) * 16;
    int bRow = T.wn * 64 + (lane & 7) + ((lane >> 4) & 1) * 8;
    int bCol = ((lane >> 3) & 1) * 16;
#pragma unroll
    for (int mi = 0; mi < 2; mi++) T.aOff[mi] = sA0 + (uint32_t)((aRow + mi * 16) * ROWB2 + aCol);
#pragma unroll
    for (int nn = 0; nn < 4; nn++) T.bOff[nn] = sB0 + (uint32_t)((bRow + nn * 16) * ROWB2 + bCol);
    // loader: 2 threads per row, 4 x 16B chunks each (row = 128 B)
    int lr = tid >> 1, lc = (tid & 1) * 4;
    T.sa = sA0 + lr * ROWB2 + lc * 16;
    T.sb = sB0 + lr * ROWB2 + lc * 16;
    T.pa = A + (size_t)(bm + lr) * D_ + lc * 8;
    T.pb = Bm + (size_t)(bn + lr) * D_ + lc * 8;
}

__device__ __forceinline__ void tile_load(const TileCtx& T, int stage, int k0) {
    uint32_t so = (uint32_t)(stage * STG2);
#pragma unroll
    for (int j = 0; j < 4; j++) cpasync16(T.sa + so + j * 16, T.pa + k0 + j * 8);
#pragma unroll
    for (int j = 0; j < 4; j++) cpasync16(T.sb + so + j * 16, T.pb + k0 + j * 8);
    asm volatile("cp.async.commit_group;\n");
}

__device__ __forceinline__ void tile_compute(const TileCtx& T, int stage, float acc[2][8][4]) {
    uint32_t soff = (uint32_t)(stage * STG2);
#pragma unroll
    for (int ks = 0; ks < 4; ks++) {
        uint32_t a[2][4];
        ldsm4(a[0][0], a[0][1], a[0][2], a[0][3], T.aOff[0] + soff + ks * 32);
        ldsm4(a[1][0], a[1][1], a[1][2], a[1][3], T.aOff[1] + soff + ks * 32);
        uint32_t b[8][2];
#pragma unroll
        for (int nn = 0; nn < 4; nn++) {
            uint32_t r0, r1, r2, r3;
            ldsm4(r0, r1, r2, r3, T.bOff[nn] + soff + ks * 32);
            b[2 * nn][0] = r0; b[2 * nn][1] = r1;
            b[2 * nn + 1][0] = r2; b[2 * nn + 1][1] = r3;
        }
#pragma unroll
        for (int mi = 0; mi < 2; mi++)
#pragma unroll
            for (int ni = 0; ni < 8; ni++)
                mma16816(acc[mi][ni], a[mi], b[ni][0], b[ni][1]);
    }
}

// ---------------- QK role (128x64 tile, dual accumulators) ----------------
struct QkCtx {
    uint32_t aOff[2], bqOff[2], bkOff[2];
    uint32_t sa, sq, sk;
    const __nv_bfloat16 *pa, *pq, *pk;
    int wm, wn, lane;
};

__device__ __forceinline__ void qk_init(QkCtx& T, uint32_t sbase, int tid,
                                        const __nv_bfloat16* A, const __nv_bfloat16* Bq,
                                        const __nv_bfloat16* Bk, int bm, int bn) {
    int lane = tid & 31, warp = tid >> 5;
    T.lane = lane;
    T.wm = warp >> 1; T.wn = warp & 1;
    uint32_t sA0 = sbase, sQ0 = sbase + A_BYTES, sK0 = sQ0 + 64 * ROWB2;
    int aRow = T.wm * 32 + (lane & 7) + ((lane >> 3) & 1) * 8;
    int aCol = ((lane >> 4) & 1) * 16;
    int bRow = T.wn * 32 + (lane & 7) + ((lane >> 4) & 1) * 8;
    int bCol = ((lane >> 3) & 1) * 16;
#pragma unroll
    for (int mi = 0; mi < 2; mi++) T.aOff[mi] = sA0 + (uint32_t)((aRow + mi * 16) * ROWB2 + aCol);
#pragma unroll
    for (int nn = 0; nn < 2; nn++) {
        T.bqOff[nn] = sQ0 + (uint32_t)((bRow + nn * 16) * ROWB2 + bCol);
        T.bkOff[nn] = sK0 + (uint32_t)((bRow + nn * 16) * ROWB2 + bCol);
    }
    // A loader: 2 threads/row, 4 chunks each. q/k loaders: 4 threads/row, 2 chunks each.
    int lr = tid >> 1, lc = (tid & 1) * 4;
    T.sa = sA0 + lr * ROWB2 + lc * 16;
    T.pa = A + (size_t)(bm + lr) * D_ + lc * 8;
    int qr = tid >> 2, qc = (tid & 3) * 2;
    T.sq = sQ0 + qr * ROWB2 + qc * 16;
    T.sk = sK0 + qr * ROWB2 + qc * 16;
    T.pq = Bq + (size_t)(bn + qr) * D_ + qc * 8;
    T.pk = Bk + (size_t)(bn + qr) * D_ + qc * 8;
}

__device__ __forceinline__ void qk_load(const QkCtx& T, int stage, int k0) {
    uint32_t so = (uint32_t)(stage * STG2);
#pragma unroll
    for (int j = 0; j < 4; j++) cpasync16(T.sa + so + j * 16, T.pa + k0 + j * 8);
#pragma unroll
    for (int j = 0; j < 2; j++) cpasync16(T.sq + so + j * 16, T.pq + k0 + j * 8);
#pragma unroll
    for (int j = 0; j < 2; j++) cpasync16(T.sk + so + j * 16, T.pk + k0 + j * 8);
    asm volatile("cp.async.commit_group;\n");
}

__device__ __forceinline__ void qk_compute(const QkCtx& T, int stage,
                                           float aq[2][4][4], float ak[2][4][4]) {
    uint32_t soff = (uint32_t)(stage * STG2);
#pragma unroll
    for (int ks = 0; ks < 4; ks++) {
        uint32_t a[2][4];
        ldsm4(a[0][0], a[0][1], a[0][2], a[0][3], T.aOff[0] + soff + ks * 32);
        ldsm4(a[1][0], a[1][1], a[1][2], a[1][3], T.aOff[1] + soff + ks * 32);
        uint32_t bq[4][2], bk[4][2];
#pragma unroll
        for (int nn = 0; nn < 2; nn++) {
            uint32_t r0, r1, r2, r3;
            ldsm4(r0, r1, r2, r3, T.bqOff[nn] + soff + ks * 32);
            bq[2 * nn][0] = r0; bq[2 * nn][1] = r1;
            bq[2 * nn + 1][0] = r2; bq[2 * nn + 1][1] = r3;
            ldsm4(r0, r1, r2, r3, T.bkOff[nn] + soff + ks * 32);
            bk[2 * nn][0] = r0; bk[2 * nn][1] = r1;
            bk[2 * nn + 1][0] = r2; bk[2 * nn + 1][1] = r3;
        }
#pragma unroll
        for (int mi = 0; mi < 2; mi++)
#pragma unroll
            for (int ni = 0; ni < 4; ni++) {
                mma16816(aq[mi][ni], a[mi], bq[ni][0], bq[ni][1]);
                mma16816(ak[mi][ni], a[mi], bk[ni][0], bk[ni][1]);
            }
    }
}

// ---------- nm term ----------
__device__ __forceinline__ float nm_term(float sim, float capm, float sapm) {
    float ca = fminf(fmaxf(sim, 0.f), 1.f);
    float sa = sqrt_approx(fminf(fmaxf(1.f - ca, 0.f), 1.f));
    float ss = sa * capm + ca * sapm;
    float cc = sqrt_approx(fminf(fmaxf(1.f - ss, 0.f), 1.f));
    return exp_approx(ss * K_COSM - cc * K_SINM);
}

// ============== mega kernel: AAM + QK roles, K-chunk 64, 8 iterations ==============
__global__ void __launch_bounds__(256, 2)
mega_gemm(const __nv_bfloat16* __restrict__ Axh, const __nv_bfloat16* __restrict__ Bw,
          const __nv_bfloat16* __restrict__ Bwm, const __nv_bfloat16* __restrict__ Bwk,
          const int* __restrict__ label) {
    extern __shared__ __align__(16) char smem[];
    uint32_t sbase = (uint32_t)__cvta_generic_to_shared(smem);
    int tid = threadIdx.x;

    if (blockIdx.x < NAAMBLK) {
        int bx = blockIdx.x % NTC, by = blockIdx.x / NTC;
        int bm = by * 128, bn = bx * 128;
        TileCtx T;
        tile_init(T, sbase, tid, Axh, Bw, bm, bn);
        float acc[2][8][4];
#pragma unroll
        for (int mi = 0; mi < 2; mi++)
#pragma unroll
            for (int ni = 0; ni < 8; ni++)
#pragma unroll
                for (int e = 0; e < 4; e++) acc[mi][ni][e] = 0.f;

        tile_load(T, 0, 0);
        tile_load(T, 1, 64);
#pragma unroll
        for (int it = 0; it < NIT2; it++) {
            if (it < NIT2 - 1) asm volatile("cp.async.wait_group 1;\n");
            else               asm volatile("cp.async.wait_group 0;\n");
            __syncthreads();
            tile_compute(T, it % NST2, acc);
            if (it + 2 < NIT2) tile_load(T, (it + 2) % NST2, (it + 2) * 64);
        }

        int lane = T.lane;
        int colbase = bn + T.wn * 64 + (lane & 3) * 2;
#pragma unroll
        for (int mi = 0; mi < 2; mi++) {
#pragma unroll
            for (int h = 0; h < 2; h++) {
                int row = bm + T.wm * 32 + mi * 16 + (lane >> 2) + h * 8;
                int lab = label[row];
                float se = 0.f, sc = 0.f, cy = 0.f;
#pragma unroll
                for (int ni = 0; ni < 8; ni++) {
                    int col = colbase + ni * 8;
                    float v0 = acc[mi][ni][h * 2 + 0];
                    float v1 = acc[mi][ni][h * 2 + 1];
                    if (col < C_) {
                        sc += v0;
                        se += exp_approx(K_S * (v0 - 1.f));
                        if (col == lab) cy = v0;
                    }
                    if (col + 1 < C_) {
                        sc += v1;
                        se += exp_approx(K_S * (v1 - 1.f));
                        if (col + 1 == lab) cy = v1;
                    }
                }
                se += __shfl_xor_sync(0xffffffffu, se, 1);
                se += __shfl_xor_sync(0xffffffffu, se, 2);
                sc += __shfl_xor_sync(0xffffffffu, sc, 1);
                sc += __shfl_xor_sync(0xffffffffu, sc, 2);
                cy += __shfl_xor_sync(0xffffffffu, cy, 1);
                cy += __shfl_xor_sync(0xffffffffu, cy, 2);
                if ((lane & 3) == 0) {
                    atomicAdd(&g_rexp[row], se);
                    atomicAdd(&g_rsum[row], sc);
                    int cb = bn + T.wn * 64;
                    if (lab >= cb && lab < cb + 64) g_cy[row] = cy;
                }
            }
        }
    } else {
        int idx = blockIdx.x - NAAMBLK;
        int cn = idx % NQCT, rm = idx / NQCT;
        int bm = rm * 128, bn = cn * 64;
        QkCtx T;
        qk_init(T, sbase, tid, Axh, Bwm, Bwk, bm, bn);
        float aq[2][4][4], ak[2][4][4];
#pragma unroll
        for (int mi = 0; mi < 2; mi++)
#pragma unroll
            for (int ni = 0; ni < 4; ni++)
#pragma unroll
                for (int e = 0; e < 4; e++) { aq[mi][ni][e] = 0.f; ak[mi][ni][e] = 0.f; }

        qk_load(T, 0, 0);
        qk_load(T, 1, 64);
#pragma unroll
        for (int it = 0; it < NIT2; it++) {
            if (it < NIT2 - 1) asm volatile("cp.async.wait_group 1;\n");
            else               asm volatile("cp.async.wait_group 0;\n");
            __syncthreads();
            qk_compute(T, it % NST2, aq, ak);
            if (it + 2 < NIT2) qk_load(T, (it + 2) % NST2, (it + 2) * 64);
        }

        __syncthreads();
        float* s_capm = (float*)smem;
        float* s_sapm = s_capm + 64;
        int*   s_lcol = (int*)(s_sapm + 64);
        int*   s_lrow = s_lcol + 64;
        if (tid < 64) {
            s_capm[tid] = g_cos_apm[bn + tid];
            s_sapm[tid] = g_sin_apm[bn + tid];
            s_lcol[tid] = label[bn + tid];
        } else if (tid < 192) {
            s_lrow[tid - 64] = label[bm + tid - 64];
        }
        __syncthreads();

        int lane = T.lane;
        int colloc0 = T.wn * 32 + (lane & 3) * 2;
#pragma unroll
        for (int mi = 0; mi < 2; mi++) {
#pragma unroll
            for (int h = 0; h < 2; h++) {
                int rloc = T.wm * 32 + mi * 16 + (lane >> 2) + h * 8;
                int row = bm + rloc;
                int lrow = s_lrow[rloc];
                float s = 0.f;
#pragma unroll
                for (int ni = 0; ni < 4; ni++) {
                    int cl = colloc0 + ni * 8;
                    float s0 = aq[mi][ni][h * 2 + 0] * ak[mi][ni][h * 2 + 0];
                    float s1 = aq[mi][ni][h * 2 + 1] * ak[mi][ni][h * 2 + 1];
                    if (s_lcol[cl] != lrow)     s += nm_term(s0, s_capm[cl], s_sapm[cl]);
                    if (s_lcol[cl + 1] != lrow) s += nm_term(s1, s_capm[cl + 1], s_sapm[cl + 1]);
                }
                s += __shfl_xor_sync(0xffffffffu, s, 1);
                s += __shfl_xor_sync(0xffffffffu, s, 2);
                if ((lane & 3) == 0)
                    atomicAdd(&g_nmp[row], s);
            }
        }
    }
}

// ---------- final combine: 8 blocks, row math parallel, last-block finish ----------
__global__ void __launch_bounds__(256)
final_combine(float* __restrict__ out) {
    int j = blockIdx.x * 256 + threadIdx.x;
    float se = g_rexp[j];
    float sc = g_rsum[j];
    float cyv = g_cy[j];
    float sine = sqrt_approx(fminf(fmaxf(1.f - cyv * cyv, 0.f), 1.f));
    float phi = cyv * K_COSM - sine * K_SINM;
    phi = (cyv - K_TH > 0.f) ? phi : (cyv - K_MM);
    float oy = K_S * phi, ocy = K_S * cyv;
    float sout = K_S * sc + (oy - ocy);
    se += exp_approx(oy - K_S) - exp_approx(ocy - K_S);
    float lse = K_S + log_approx(se);
    float sa = (1.f - K_EPS) * (oy - lse) + (K_EPS / C_) * sout - K_EPS * lse;
    float sn = g_expneg[j];
    float sm = g_nmp[j];
    sa = block_sum_all(sa);
    sn = block_sum_all(sn);
    sm = block_sum_all(sm);
    if (threadIdx.x == 0) {
        atomicAdd(&g_acc[0], sa);
        atomicAdd(&g_acc[1], sn);
        atomicAdd(&g_acc[2], sm);
        __threadfence();
        unsigned t = atomicAdd(&g_ticket, 1u);
        if (t == NFINAL - 1) {
            float fsa = g_acc[0], fsn = g_acc[1], fsm = g_acc[2];
            float aam_loss = -fsa / (float)B_;
            float z = logf(fsm) + logf(fsn);
            float cc = fmaxf(z, 0.f) + log1pf(expf(-fabsf(z)));
            out[0] = aam_loss + cc;
        }
    }
}

// ---------- launcher: 3 launches ----------
extern "C" void kernel_launch(void* const* d_in, const int* in_sizes, int n_in,
                              void* d_out, int out_size) {
    const float* x        = (const float*)d_in[0];
    const int*   label    = (const int*)d_in[1];
    const float* weight   = (const float*)d_in[2];
    const float* weight_m = (const float*)d_in[3];
    const float* weight_n = (const float*)d_in[4];
    float* out = (float*)d_out;

    __nv_bfloat16 *p_xh, *p_wh, *p_wmh, *p_wkh;
    cudaGetSymbolAddress((void**)&p_xh,  g_xh);
    cudaGetSymbolAddress((void**)&p_wh,  g_wh);
    cudaGetSymbolAddress((void**)&p_wmh, g_wmh);
    cudaGetSymbolAddress((void**)&p_wkh, g_wkh);

    cudaFuncSetAttribute(mega_gemm, cudaFuncAttributeMaxDynamicSharedMemorySize, GEMM_SMEM);

    prep_kernel<<<PREP_GRID, 256>>>(x, weight, weight_m, weight_n, label);
    mega_gemm<<<NMEGA, 256, GEMM_SMEM>>>(p_xh, p_wh, p_wmh, p_wkh, label);
    final_combine<<<NFINAL, 256>>>(out);
}

// round 14
// speedup vs baseline: 1.2760x; 1.2760x over previous
#include <cuda_runtime.h>
#include <cuda_bf16.h>
#include <math.h>
#include <stdint.h>

#define B_ 2048
#define D_ 512
#define C_ 10000
#define CPAD 10112          // 79 * 128
#define NTC 79              // AAM col tiles of 128
#define NQCT 32             // QK col tiles of 64
#define NAAMBLK (NTC * (B_ / 128))        // 1264
#define NQKBLK  (NQCT * (B_ / 128))       // 512
#define NMEGA (NAAMBLK + NQKBLK)          // 1776
#define NFINAL 8

// ---------- scratch (device globals: alloc-free, capture-safe) ----------
__device__ __nv_bfloat16 g_xh[B_ * D_];
__device__ __nv_bfloat16 g_wh[(size_t)CPAD * D_];
__device__ __nv_bfloat16 g_wmh[B_ * D_];
__device__ __nv_bfloat16 g_wkh[B_ * D_];
__device__ float g_rexp[B_];
__device__ float g_rsum[B_];
__device__ float g_nmp[B_];
__device__ float g_cy[B_];
__device__ float g_expneg[B_];
__device__ float g_cos_apm[B_];
__device__ float g_sin_apm[B_];
__device__ float g_acc[3];
__device__ unsigned g_ticket;

// ---------- constants ----------
constexpr float K_S    = 30.0f;
constexpr float K_COSM = 0.9800665778412416f;
constexpr float K_SINM = 0.19866933079506122f;
constexpr float K_TH   = -0.9800665778412416f;
constexpr float K_MM   = 0.039733866159012244f;
constexpr float K_EPS  = 0.1f;
constexpr float K_L2E  = 1.4426950408889634f;
constexpr float K_LN2  = 0.6931471805599453f;

// ---------- fast math (MUFU) ----------
__device__ __forceinline__ float exp_approx(float x) {
    float r;
    asm("ex2.approx.f32 %0, %1;" : "=f"(r) : "f"(x * K_L2E));
    return r;
}
__device__ __forceinline__ float log_approx(float x) {
    float r;
    asm("lg2.approx.f32 %0, %1;" : "=f"(r) : "f"(x));
    return r * K_LN2;
}
__device__ __forceinline__ float sqrt_approx(float x) {
    float r;
    asm("sqrt.approx.f32 %0, %1;" : "=f"(r) : "f"(x));
    return r;
}

// ---------- block-wide sum (final_combine only) ----------
__device__ __forceinline__ float block_sum_all(float v) {
    __shared__ float sh[33];
    int lane = threadIdx.x & 31, wid = threadIdx.x >> 5;
#pragma unroll
    for (int o = 16; o; o >>= 1) v += __shfl_down_sync(0xffffffffu, v, o);
    __syncthreads();
    if (lane == 0) sh[wid] = v;
    __syncthreads();
    if (threadIdx.x == 0) {
        float s = 0.f;
        int nw = (blockDim.x + 31) >> 5;
        for (int w = 0; w < nw; w++) s += sh[w];
        sh[32] = s;
    }
    __syncthreads();
    return sh[32];
}

// ---------- warp-per-row L2 normalize -> bf16 (no block barriers) ----------
__device__ __forceinline__ void warp_norm(const float* __restrict__ src,
                                          __nv_bfloat16* __restrict__ dst, int lane) {
    const float4* sp = (const float4*)src + lane * 4;
    float4 v[4];
    float ss = 0.f;
#pragma unroll
    for (int e = 0; e < 4; e++) {
        v[e] = sp[e];
        ss += v[e].x * v[e].x + v[e].y * v[e].y + v[e].z * v[e].z + v[e].w * v[e].w;
    }
#pragma unroll
    for (int o = 16; o; o >>= 1) ss += __shfl_xor_sync(0xffffffffu, ss, o);
    float inv = 1.0f / fmaxf(sqrtf(ss), 1e-12f);
    uint32_t po[8];
#pragma unroll
    for (int e = 0; e < 4; e++) {
        __nv_bfloat162 p0 = __floats2bfloat162_rn(v[e].x * inv, v[e].y * inv);
        __nv_bfloat162 p1 = __floats2bfloat162_rn(v[e].z * inv, v[e].w * inv);
        po[2 * e + 0] = *(uint32_t*)&p0;
        po[2 * e + 1] = *(uint32_t*)&p1;
    }
    uint4* dp = (uint4*)(dst + lane * 16);
    dp[0] = make_uint4(po[0], po[1], po[2], po[3]);
    dp[1] = make_uint4(po[4], po[5], po[6], po[7]);
}

__device__ __forceinline__ void write_norm_bf16(const float4* v, float inv,
                                                __nv_bfloat16* dst, int lane) {
    uint32_t po[8];
#pragma unroll
    for (int e = 0; e < 4; e++) {
        __nv_bfloat162 p0 = __floats2bfloat162_rn(v[e].x * inv, v[e].y * inv);
        __nv_bfloat162 p1 = __floats2bfloat162_rn(v[e].z * inv, v[e].w * inv);
        po[2 * e + 0] = *(uint32_t*)&p0;
        po[2 * e + 1] = *(uint32_t*)&p1;
    }
    uint4* dp = (uint4*)(dst + lane * 16);
    dp[0] = make_uint4(po[0], po[1], po[2], po[3]);
    dp[1] = make_uint4(po[4], po[5], po[6], po[7]);
}

// prep roles:
//  blocks [0, NB_NORM): 8 warps/block, warp per row of {w | x | wm&wk gather+apm}
//  blocks [NB_NORM, NB_NORM+8): zero accumulators (+ first: g_acc/g_ticket)
#define NROWS_NORM (CPAD + B_ + B_)          // 14208
#define NB_NORM (NROWS_NORM / 8)             // 1776
#define NB_ZERO 8
#define PREP_GRID (NB_NORM + NB_ZERO)

__global__ void __launch_bounds__(256)
prep_kernel(const float* __restrict__ x, const float* __restrict__ w,
            const float* __restrict__ wm, const float* __restrict__ wk,
            const int* __restrict__ label) {
    int b = blockIdx.x, t = threadIdx.x;
    int wv = t >> 5, lane = t & 31;
    if (b < NB_NORM) {
        int row = b * 8 + wv;
        if (row < CPAD) {
            __nv_bfloat16* dst = g_wh + (size_t)row * D_;
            if (row >= C_) {
                uint4* dp = (uint4*)(dst + lane * 16);
                uint4 z = make_uint4(0u, 0u, 0u, 0u);
                dp[0] = z; dp[1] = z;
            } else {
                warp_norm(w + (size_t)row * D_, dst, lane);
            }
        } else if (row < CPAD + B_) {
            int r = row - CPAD;
            warp_norm(x + (size_t)r * D_, g_xh + (size_t)r * D_, lane);
        } else {
            // gather + normalize wm/wk AND compute apm (ap_m == ap exactly;
            // all label-matched sim values are identical) in one pass.
            int i = row - CPAD - B_;
            int c = label[i];
            const float4* xp = (const float4*)(x  + (size_t)i * D_) + lane * 4;
            const float4* qp = (const float4*)(wm + (size_t)c * D_) + lane * 4;
            const float4* kp = (const float4*)(wk + (size_t)c * D_) + lane * 4;
            float4 qv[4], kv[4];
            float xx = 0.f, xq = 0.f, qq = 0.f, xk = 0.f, kk = 0.f;
#pragma unroll
            for (int e = 0; e < 4; e++) {
                float4 xv = xp[e];
                qv[e] = qp[e];
                kv[e] = kp[e];
                xx += xv.x * xv.x + xv.y * xv.y + xv.z * xv.z + xv.w * xv.w;
                xq += xv.x * qv[e].x + xv.y * qv[e].y + xv.z * qv[e].z + xv.w * qv[e].w;
                qq += qv[e].x * qv[e].x + qv[e].y * qv[e].y + qv[e].z * qv[e].z + qv[e].w * qv[e].w;
                xk += xv.x * kv[e].x + xv.y * kv[e].y + xv.z * kv[e].z + xv.w * kv[e].w;
                kk += kv[e].x * kv[e].x + kv[e].y * kv[e].y + kv[e].z * kv[e].z + kv[e].w * kv[e].w;
            }
#pragma unroll
            for (int o = 16; o; o >>= 1) {
                xx += __shfl_xor_sync(0xffffffffu, xx, o);
                xq += __shfl_xor_sync(0xffffffffu, xq, o);
                qq += __shfl_xor_sync(0xffffffffu, qq, o);
                xk += __shfl_xor_sync(0xffffffffu, xk, o);
                kk += __shfl_xor_sync(0xffffffffu, kk, o);
            }
            float invq = 1.0f / fmaxf(sqrtf(qq), 1e-12f);
            float invk = 1.0f / fmaxf(sqrtf(kk), 1e-12f);
            write_norm_bf16(qv, invq, g_wmh + (size_t)i * D_, lane);
            write_norm_bf16(kv, invk, g_wkh + (size_t)i * D_, lane);
            if (lane == 0) {
                float dq = xq / fmaxf(sqrtf(xx * qq), 1e-24f);
                float dk = xk / fmaxf(sqrtf(xx * kk), 1e-24f);
                float ap = dq * dk;                 // == ap_m exactly
                float ca = fminf(fmaxf(ap, 0.f), 1.f);
                float sa = sqrt_approx(fminf(fmaxf(1.f - ca, 0.f), 1.f));
                g_cos_apm[i] = ca;
                g_sin_apm[i] = sa;
                float pc = ca * ca - sa * sa;       // cos_ap == cos_apm
                float ps = sqrt_approx(fminf(fmaxf(1.f - pc, 0.f), 1.f));
                float phi_pm = pc * K_COSM - ps * K_SINM;
                g_expneg[i] = exp_approx(1.f - phi_pm);
            }
        }
    } else {
        int idx = (b - NB_NORM) * 256 + t;
        g_rexp[idx] = 0.f;
        g_rsum[idx] = 0.f;
        g_nmp[idx]  = 0.f;
        if (b == NB_NORM) {
            if (t < 3) g_acc[t] = 0.f;
            if (t == 3) g_ticket = 0u;
        }
    }
}

// ============== mma.sync bf16 building blocks (R12 proven config) ==============
__device__ __forceinline__ void ldsm4(uint32_t& r0, uint32_t& r1, uint32_t& r2, uint32_t& r3,
                                      uint32_t addr) {
    asm volatile("ldmatrix.sync.aligned.m8n8.x4.shared.b16 {%0,%1,%2,%3},[%4];\n"
                 : "=r"(r0), "=r"(r1), "=r"(r2), "=r"(r3) : "r"(addr));
}
__device__ __forceinline__ void mma16816(float* c, const uint32_t* a, uint32_t b0, uint32_t b1) {
    asm volatile("mma.sync.aligned.m16n8k16.row.col.f32.bf16.bf16.f32 "
                 "{%0,%1,%2,%3},{%4,%5,%6,%7},{%8,%9},{%0,%1,%2,%3};\n"
                 : "+f"(c[0]), "+f"(c[1]), "+f"(c[2]), "+f"(c[3])
                 : "r"(a[0]), "r"(a[1]), "r"(a[2]), "r"(a[3]), "r"(b0), "r"(b1));
}
__device__ __forceinline__ void cpasync16(uint32_t s, const void* g) {
    asm volatile("cp.async.cg.shared.global [%0],[%1],16;\n" :: "r"(s), "l"(g));
}

#define ROWB 80
#define HALFB (128 * ROWB)
#define STAGEB (256 * ROWB)         // 20480 B
#define NSTAGE 4
#define GEMM_SMEM (NSTAGE * STAGEB) // 81920 B
#define NIT_ 16
#define WAITS(it) do {                                                     \
    if ((it) <= NIT_ - 3)      asm volatile("cp.async.wait_group 2;\n");   \
    else if ((it) == NIT_ - 2) asm volatile("cp.async.wait_group 1;\n");   \
    else                       asm volatile("cp.async.wait_group 0;\n");   \
} while (0)

// ---------------- AAM role (128x128 tile) ----------------
struct TileCtx {
    uint32_t aOff[2], bOff[4];
    uint32_t sa0, sa1, sb0, sb1;
    const __nv_bfloat16 *pa0, *pa1, *pb0, *pb1;
    int wm, wn, lane;
};

__device__ __forceinline__ void tile_init(TileCtx& T, uint32_t sbase, int tid,
                                          const __nv_bfloat16* A, const __nv_bfloat16* Bm,
                                          int bm, int bn) {
    int lane = tid & 31, warp = tid >> 5;
    T.lane = lane;
    T.wm = warp >> 1; T.wn = warp & 1;
    uint32_t sA0 = sbase, sB0 = sbase + HALFB;
    int aRow = T.wm * 32 + (lane & 7) + ((lane >> 3) & 1) * 8;
    int aCol = ((lane >> 4) & 1) * 16;
    int bRow = T.wn * 64 + (lane & 7) + ((lane >> 4) & 1) * 8;
    int bCol = ((lane >> 3) & 1) * 16;
#pragma unroll
    for (int mi = 0; mi < 2; mi++) T.aOff[mi] = sA0 + (uint32_t)((aRow + mi * 16) * ROWB + aCol);
#pragma unroll
    for (int nn = 0; nn < 4; nn++) T.bOff[nn] = sB0 + (uint32_t)((bRow + nn * 16) * ROWB + bCol);
    int c0r = tid >> 2, c0k = tid & 3;
    T.sa0 = sA0 + c0r * ROWB + c0k * 16;
    T.sa1 = sA0 + (c0r + 64) * ROWB + c0k * 16;
    T.sb0 = sB0 + c0r * ROWB + c0k * 16;
    T.sb1 = sB0 + (c0r + 64) * ROWB + c0k * 16;
    T.pa0 = A + (size_t)(bm + c0r) * D_ + c0k * 8;
    T.pa1 = A + (size_t)(bm + c0r + 64) * D_ + c0k * 8;
    T.pb0 = Bm + (size_t)(bn + c0r) * D_ + c0k * 8;
    T.pb1 = Bm + (size_t)(bn + c0r + 64) * D_ + c0k * 8;
}

__device__ __forceinline__ void tile_load(const TileCtx& T, int stage, int k0) {
    uint32_t so = (uint32_t)(stage * STAGEB);
    cpasync16(T.sa0 + so, T.pa0 + k0);
    cpasync16(T.sa1 + so, T.pa1 + k0);
    cpasync16(T.sb0 + so, T.pb0 + k0);
    cpasync16(T.sb1 + so, T.pb1 + k0);
    asm volatile("cp.async.commit_group;\n");
}

__device__ __forceinline__ void tile_compute(const TileCtx& T, int stage, float acc[2][8][4]) {
    uint32_t soff = (uint32_t)(stage * STAGEB);
#pragma unroll
    for (int ks = 0; ks < 2; ks++) {
        uint32_t a[2][4];
        ldsm4(a[0][0], a[0][1], a[0][2], a[0][3], T.aOff[0] + soff + ks * 32);
        ldsm4(a[1][0], a[1][1], a[1][2], a[1][3], T.aOff[1] + soff + ks * 32);
        uint32_t b[8][2];
#pragma unroll
        for (int nn = 0; nn < 4; nn++) {
            uint32_t r0, r1, r2, r3;
            ldsm4(r0, r1, r2, r3, T.bOff[nn] + soff + ks * 32);
            b[2 * nn][0] = r0; b[2 * nn][1] = r1;
            b[2 * nn + 1][0] = r2; b[2 * nn + 1][1] = r3;
        }
#pragma unroll
        for (int mi = 0; mi < 2; mi++)
#pragma unroll
            for (int ni = 0; ni < 8; ni++)
                mma16816(acc[mi][ni], a[mi], b[ni][0], b[ni][1]);
    }
}

// ---------------- QK role (128x64 tile, dual accumulators) ----------------
struct QkCtx {
    uint32_t aOff[2], bqOff[2], bkOff[2];
    uint32_t sa0, sa1, sq, sk;
    const __nv_bfloat16 *pa0, *pa1, *pq, *pk;
    int wm, wn, lane;
};

__device__ __forceinline__ void qk_init(QkCtx& T, uint32_t sbase, int tid,
                                        const __nv_bfloat16* A, const __nv_bfloat16* Bq,
                                        const __nv_bfloat16* Bk, int bm, int bn) {
    int lane = tid & 31, warp = tid >> 5;
    T.lane = lane;
    T.wm = warp >> 1; T.wn = warp & 1;
    uint32_t sA0 = sbase, sQ0 = sbase + HALFB, sK0 = sbase + HALFB + 64 * ROWB;
    int aRow = T.wm * 32 + (lane & 7) + ((lane >> 3) & 1) * 8;
    int aCol = ((lane >> 4) & 1) * 16;
    int bRow = T.wn * 32 + (lane & 7) + ((lane >> 4) & 1) * 8;
    int bCol = ((lane >> 3) & 1) * 16;
#pragma unroll
    for (int mi = 0; mi < 2; mi++) T.aOff[mi] = sA0 + (uint32_t)((aRow + mi * 16) * ROWB + aCol);
#pragma unroll
    for (int nn = 0; nn < 2; nn++) {
        T.bqOff[nn] = sQ0 + (uint32_t)((bRow + nn * 16) * ROWB + bCol);
        T.bkOff[nn] = sK0 + (uint32_t)((bRow + nn * 16) * ROWB + bCol);
    }
    int c0r = tid >> 2, c0k = tid & 3;
    T.sa0 = sA0 + c0r * ROWB + c0k * 16;
    T.sa1 = sA0 + (c0r + 64) * ROWB + c0k * 16;
    T.sq  = sQ0 + c0r * ROWB + c0k * 16;
    T.sk  = sK0 + c0r * ROWB + c0k * 16;
    T.pa0 = A  + (size_t)(bm + c0r) * D_ + c0k * 8;
    T.pa1 = A  + (size_t)(bm + c0r + 64) * D_ + c0k * 8;
    T.pq  = Bq + (size_t)(bn + c0r) * D_ + c0k * 8;
    T.pk  = Bk + (size_t)(bn + c0r) * D_ + c0k * 8;
}

__device__ __forceinline__ void qk_load(const QkCtx& T, int stage, int k0) {
    uint32_t so = (uint32_t)(stage * STAGEB);
    cpasync16(T.sa0 + so, T.pa0 + k0);
    cpasync16(T.sa1 + so, T.pa1 + k0);
    cpasync16(T.sq  + so, T.pq  + k0);
    cpasync16(T.sk  + so, T.pk  + k0);
    asm volatile("cp.async.commit_group;\n");
}

__device__ __forceinline__ void qk_compute(const QkCtx& T, int stage,
                                           float aq[2][4][4], float ak[2][4][4]) {
    uint32_t soff = (uint32_t)(stage * STAGEB);
#pragma unroll
    for (int ks = 0; ks < 2; ks++) {
        uint32_t a[2][4];
        ldsm4(a[0][0], a[0][1], a[0][2], a[0][3], T.aOff[0] + soff + ks * 32);
        ldsm4(a[1][0], a[1][1], a[1][2], a[1][3], T.aOff[1] + soff + ks * 32);
        uint32_t bq[4][2], bk[4][2];
#pragma unroll
        for (int nn = 0; nn < 2; nn++) {
            uint32_t r0, r1, r2, r3;
            ldsm4(r0, r1, r2, r3, T.bqOff[nn] + soff + ks * 32);
            bq[2 * nn][0] = r0; bq[2 * nn][1] = r1;
            bq[2 * nn + 1][0] = r2; bq[2 * nn + 1][1] = r3;
            ldsm4(r0, r1, r2, r3, T.bkOff[nn] + soff + ks * 32);
            bk[2 * nn][0] = r0; bk[2 * nn][1] = r1;
            bk[2 * nn + 1][0] = r2; bk[2 * nn + 1][1] = r3;
        }
#pragma unroll
        for (int mi = 0; mi < 2; mi++)
#pragma unroll
            for (int ni = 0; ni < 4; ni++) {
                mma16816(aq[mi][ni], a[mi], bq[ni][0], bq[ni][1]);
                mma16816(ak[mi][ni], a[mi], bk[ni][0], bk[ni][1]);
            }
    }
}

// ---------- nm term ----------
__device__ __forceinline__ float nm_term(float sim, float capm, float sapm) {
    float ca = fminf(fmaxf(sim, 0.f), 1.f);
    float sa = sqrt_approx(fminf(fmaxf(1.f - ca, 0.f), 1.f));
    float ss = sa * capm + ca * sapm;
    float cc = sqrt_approx(fminf(fmaxf(1.f - ss, 0.f), 1.f));
    return exp_approx(ss * K_COSM - cc * K_SINM);
}

// ============== mega kernel: AAM blocks + QK blocks, atomic row accumulation ==============
__global__ void __launch_bounds__(256, 2)
mega_gemm(const __nv_bfloat16* __restrict__ Axh, const __nv_bfloat16* __restrict__ Bw,
          const __nv_bfloat16* __restrict__ Bwm, const __nv_bfloat16* __restrict__ Bwk,
          const int* __restrict__ label) {
    extern __shared__ __align__(16) char smem[];
    uint32_t sbase = (uint32_t)__cvta_generic_to_shared(smem);
    int tid = threadIdx.x;

    if (blockIdx.x < NAAMBLK) {
        int bx = blockIdx.x % NTC, by = blockIdx.x / NTC;
        int bm = by * 128, bn = bx * 128;
        TileCtx T;
        tile_init(T, sbase, tid, Axh, Bw, bm, bn);
        float acc[2][8][4];
#pragma unroll
        for (int mi = 0; mi < 2; mi++)
#pragma unroll
            for (int ni = 0; ni < 8; ni++)
#pragma unroll
                for (int e = 0; e < 4; e++) acc[mi][ni][e] = 0.f;

        tile_load(T, 0, 0);
        tile_load(T, 1, 32);
        tile_load(T, 2, 64);
#pragma unroll
        for (int it = 0; it < NIT_; it++) {
            WAITS(it);
            __syncthreads();
            tile_compute(T, it & 3, acc);
            if (it + 3 < NIT_) tile_load(T, (it + 3) & 3, (it + 3) * 32);
        }

        int lane = T.lane;
        int colbase = bn + T.wn * 64 + (lane & 3) * 2;
#pragma unroll
        for (int mi = 0; mi < 2; mi++) {
#pragma unroll
            for (int h = 0; h < 2; h++) {
                int row = bm + T.wm * 32 + mi * 16 + (lane >> 2) + h * 8;
                int lab = label[row];
                float se = 0.f, sc = 0.f, cy = 0.f;
#pragma unroll
                for (int ni = 0; ni < 8; ni++) {
                    int col = colbase + ni * 8;
                    float v0 = acc[mi][ni][h * 2 + 0];
                    float v1 = acc[mi][ni][h * 2 + 1];
                    if (col < C_) {
                        sc += v0;
                        se += exp_approx(K_S * (v0 - 1.f));
                        if (col == lab) cy = v0;
                    }
                    if (col + 1 < C_) {
                        sc += v1;
                        se += exp_approx(K_S * (v1 - 1.f));
                        if (col + 1 == lab) cy = v1;
                    }
                }
                se += __shfl_xor_sync(0xffffffffu, se, 1);
                se += __shfl_xor_sync(0xffffffffu, se, 2);
                sc += __shfl_xor_sync(0xffffffffu, sc, 1);
                sc += __shfl_xor_sync(0xffffffffu, sc, 2);
                cy += __shfl_xor_sync(0xffffffffu, cy, 1);
                cy += __shfl_xor_sync(0xffffffffu, cy, 2);
                if ((lane & 3) == 0) {
                    atomicAdd(&g_rexp[row], se);
                    atomicAdd(&g_rsum[row], sc);
                    int cb = bn + T.wn * 64;
                    if (lab >= cb && lab < cb + 64) g_cy[row] = cy;
                }
            }
        }
    } else {
        int idx = blockIdx.x - NAAMBLK;
        int cn = idx % NQCT, rm = idx / NQCT;
        int bm = rm * 128, bn = cn * 64;
        QkCtx T;
        qk_init(T, sbase, tid, Axh, Bwm, Bwk, bm, bn);
        float aq[2][4][4], ak[2][4][4];
#pragma unroll
        for (int mi = 0; mi < 2; mi++)
#pragma unroll
            for (int ni = 0; ni < 4; ni++)
#pragma unroll
                for (int e = 0; e < 4; e++) { aq[mi][ni][e] = 0.f; ak[mi][ni][e] = 0.f; }

        qk_load(T, 0, 0);
        qk_load(T, 1, 32);
        qk_load(T, 2, 64);
#pragma unroll
        for (int it = 0; it < NIT_; it++) {
            WAITS(it);
            __syncthreads();
            qk_compute(T, it & 3, aq, ak);
            if (it + 3 < NIT_) qk_load(T, (it + 3) & 3, (it + 3) * 32);
        }

        __syncthreads();
        float* s_capm = (float*)smem;
        float* s_sapm = s_capm + 64;
        int*   s_lcol = (int*)(s_sapm + 64);
        int*   s_lrow = s_lcol + 64;
        if (tid < 64) {
            s_capm[tid] = g_cos_apm[bn + tid];
            s_sapm[tid] = g_sin_apm[bn + tid];
            s_lcol[tid] = label[bn + tid];
        } else if (tid < 192) {
            s_lrow[tid - 64] = label[bm + tid - 64];
        }
        __syncthreads();

        int lane = T.lane;
        int colloc0 = T.wn * 32 + (lane & 3) * 2;
#pragma unroll
        for (int mi = 0; mi < 2; mi++) {
#pragma unroll
            for (int h = 0; h < 2; h++) {
                int rloc = T.wm * 32 + mi * 16 + (lane >> 2) + h * 8;
                int row = bm + rloc;
                int lrow = s_lrow[rloc];
                float s = 0.f;
#pragma unroll
                for (int ni = 0; ni < 4; ni++) {
                    int cl = colloc0 + ni * 8;
                    float s0 = aq[mi][ni][h * 2 + 0] * ak[mi][ni][h * 2 + 0];
                    float s1 = aq[mi][ni][h * 2 + 1] * ak[mi][ni][h * 2 + 1];
                    if (s_lcol[cl] != lrow)     s += nm_term(s0, s_capm[cl], s_sapm[cl]);
                    if (s_lcol[cl + 1] != lrow) s += nm_term(s1, s_capm[cl + 1], s_sapm[cl + 1]);
                }
                s += __shfl_xor_sync(0xffffffffu, s, 1);
                s += __shfl_xor_sync(0xffffffffu, s, 2);
                if ((lane & 3) == 0)
                    atomicAdd(&g_nmp[row], s);
            }
        }
    }
}

// ---------- final combine: 8 blocks, row math parallel, last-block finish ----------
__global__ void __launch_bounds__(256)
final_combine(float* __restrict__ out) {
    int j = blockIdx.x * 256 + threadIdx.x;
    float se = g_rexp[j];
    float sc = g_rsum[j];
    float cyv = g_cy[j];
    float sine = sqrt_approx(fminf(fmaxf(1.f - cyv * cyv, 0.f), 1.f));
    float phi = cyv * K_COSM - sine * K_SINM;
    phi = (cyv - K_TH > 0.f) ? phi : (cyv - K_MM);
    float oy = K_S * phi, ocy = K_S * cyv;
    float sout = K_S * sc + (oy - ocy);
    se += exp_approx(oy - K_S) - exp_approx(ocy - K_S);
    float lse = K_S + log_approx(se);
    float sa = (1.f - K_EPS) * (oy - lse) + (K_EPS / C_) * sout - K_EPS * lse;
    float sn = g_expneg[j];
    float sm = g_nmp[j];
    sa = block_sum_all(sa);
    sn = block_sum_all(sn);
    sm = block_sum_all(sm);
    if (threadIdx.x == 0) {
        atomicAdd(&g_acc[0], sa);
        atomicAdd(&g_acc[1], sn);
        atomicAdd(&g_acc[2], sm);
        __threadfence();
        unsigned t = atomicAdd(&g_ticket, 1u);
        if (t == NFINAL - 1) {
            float fsa = g_acc[0], fsn = g_acc[1], fsm = g_acc[2];
            float aam_loss = -fsa / (float)B_;
            float z = logf(fsm) + logf(fsn);
            float cc = fmaxf(z, 0.f) + log1pf(expf(-fabsf(z)));
            out[0] = aam_loss + cc;
        }
    }
}

// ---------- launcher: 3 launches ----------
extern "C" void kernel_launch(void* const* d_in, const int* in_sizes, int n_in,
                              void* d_out, int out_size) {
    const float* x        = (const float*)d_in[0];
    const int*   label    = (const int*)d_in[1];
    const float* weight   = (const float*)d_in[2];
    const float* weight_m = (const float*)d_in[3];
    const float* weight_n = (const float*)d_in[4];
    float* out = (float*)d_out;

    __nv_bfloat16 *p_xh, *p_wh, *p_wmh, *p_wkh;
    cudaGetSymbolAddress((void**)&p_xh,  g_xh);
    cudaGetSymbolAddress((void**)&p_wh,  g_wh);
    cudaGetSymbolAddress((void**)&p_wmh, g_wmh);
    cudaGetSymbolAddress((void**)&p_wkh, g_wkh);

    cudaFuncSetAttribute(mega_gemm, cudaFuncAttributeMaxDynamicSharedMemorySize, GEMM_SMEM);

    prep_kernel<<<PREP_GRID, 256>>>(x, weight, weight_m, weight_n, label);
    mega_gemm<<<NMEGA, 256, GEMM_SMEM>>>(p_xh, p_wh, p_wmh, p_wkh, label);
    final_combine<<<NFINAL, 256>>>(out);
}

// round 15
// speedup vs baseline: 1.2768x; 1.0006x over previous
#include <cuda_runtime.h>
#include <cuda_bf16.h>
#include <math.h>
#include <stdint.h>

#define B_ 2048
#define D_ 512
#define C_ 10000
#define CPAD 10112          // 79 * 128
#define NTC 79              // AAM col tiles of 128
#define NQCT 32             // QK col tiles of 64
#define NAAMBLK (NTC * (B_ / 128))        // 1264
#define NQKBLK  (NQCT * (B_ / 128))       // 512
#define NMEGA (NAAMBLK + NQKBLK)          // 1776
#define NFINAL 8

// ---------- scratch (device globals: alloc-free, capture-safe) ----------
__device__ __nv_bfloat16 g_xh[B_ * D_];
__device__ __nv_bfloat16 g_wh[(size_t)CPAD * D_];
__device__ __nv_bfloat16 g_wmh[B_ * D_];
__device__ __nv_bfloat16 g_wkh[B_ * D_];
__device__ float g_rexp[B_];
__device__ float g_rsum[B_];
__device__ float g_nmp[B_];
__device__ float g_cy[B_];
__device__ float g_expneg[B_];
__device__ float g_cos_apm[B_];
__device__ float g_sin_apm[B_];
__device__ float g_acc[3];
__device__ unsigned g_ticket;

// ---------- constants ----------
constexpr float K_S    = 30.0f;
constexpr float K_COSM = 0.9800665778412416f;
constexpr float K_SINM = 0.19866933079506122f;
constexpr float K_TH   = -0.9800665778412416f;
constexpr float K_MM   = 0.039733866159012244f;
constexpr float K_EPS  = 0.1f;
constexpr float K_L2E  = 1.4426950408889634f;
constexpr float K_LN2  = 0.6931471805599453f;

// ---------- fast math (MUFU) ----------
__device__ __forceinline__ float exp_approx(float x) {
    float r;
    asm("ex2.approx.f32 %0, %1;" : "=f"(r) : "f"(x * K_L2E));
    return r;
}
__device__ __forceinline__ float log_approx(float x) {
    float r;
    asm("lg2.approx.f32 %0, %1;" : "=f"(r) : "f"(x));
    return r * K_LN2;
}
__device__ __forceinline__ float sqrt_approx(float x) {
    float r;
    asm("sqrt.approx.f32 %0, %1;" : "=f"(r) : "f"(x));
    return r;
}

// ---------- block-wide sum (final_combine only) ----------
__device__ __forceinline__ float block_sum_all(float v) {
    __shared__ float sh[33];
    int lane = threadIdx.x & 31, wid = threadIdx.x >> 5;
#pragma unroll
    for (int o = 16; o; o >>= 1) v += __shfl_down_sync(0xffffffffu, v, o);
    __syncthreads();
    if (lane == 0) sh[wid] = v;
    __syncthreads();
    if (threadIdx.x == 0) {
        float s = 0.f;
        int nw = (blockDim.x + 31) >> 5;
        for (int w = 0; w < nw; w++) s += sh[w];
        sh[32] = s;
    }
    __syncthreads();
    return sh[32];
}

// ---------- warp-per-row normalize helpers ----------
__device__ __forceinline__ void write_norm_bf16(const float4* v, float inv,
                                                __nv_bfloat16* dst, int lane) {
    uint32_t po[8];
#pragma unroll
    for (int e = 0; e < 4; e++) {
        __nv_bfloat162 p0 = __floats2bfloat162_rn(v[e].x * inv, v[e].y * inv);
        __nv_bfloat162 p1 = __floats2bfloat162_rn(v[e].z * inv, v[e].w * inv);
        po[2 * e + 0] = *(uint32_t*)&p0;
        po[2 * e + 1] = *(uint32_t*)&p1;
    }
    uint4* dp = (uint4*)(dst + lane * 16);
    dp[0] = make_uint4(po[0], po[1], po[2], po[3]);
    dp[1] = make_uint4(po[4], po[5], po[6], po[7]);
}

__device__ __forceinline__ void warp_norm(const float* __restrict__ src,
                                          __nv_bfloat16* __restrict__ dst, int lane) {
    const float4* sp = (const float4*)src + lane * 4;
    float4 v[4];
    float ss = 0.f;
#pragma unroll
    for (int e = 0; e < 4; e++) {
        v[e] = sp[e];
        ss += v[e].x * v[e].x + v[e].y * v[e].y + v[e].z * v[e].z + v[e].w * v[e].w;
    }
#pragma unroll
    for (int o = 16; o; o >>= 1) ss += __shfl_xor_sync(0xffffffffu, ss, o);
    write_norm_bf16(v, 1.0f / fmaxf(sqrtf(ss), 1e-12f), dst, lane);
}

// two independent rows per warp: 8 front-batched LDG.128, dual shuffle chains
__device__ __forceinline__ void warp_norm2(const float* __restrict__ s0,
                                           const float* __restrict__ s1,
                                           __nv_bfloat16* __restrict__ d0,
                                           __nv_bfloat16* __restrict__ d1, int lane) {
    const float4* p0 = (const float4*)s0 + lane * 4;
    const float4* p1 = (const float4*)s1 + lane * 4;
    float4 v0[4], v1[4];
#pragma unroll
    for (int e = 0; e < 4; e++) v0[e] = p0[e];
#pragma unroll
    for (int e = 0; e < 4; e++) v1[e] = p1[e];
    float ss0 = 0.f, ss1 = 0.f;
#pragma unroll
    for (int e = 0; e < 4; e++) {
        ss0 += v0[e].x * v0[e].x + v0[e].y * v0[e].y + v0[e].z * v0[e].z + v0[e].w * v0[e].w;
        ss1 += v1[e].x * v1[e].x + v1[e].y * v1[e].y + v1[e].z * v1[e].z + v1[e].w * v1[e].w;
    }
#pragma unroll
    for (int o = 16; o; o >>= 1) {
        ss0 += __shfl_xor_sync(0xffffffffu, ss0, o);
        ss1 += __shfl_xor_sync(0xffffffffu, ss1, o);
    }
    write_norm_bf16(v0, 1.0f / fmaxf(sqrtf(ss0), 1e-12f), d0, lane);
    write_norm_bf16(v1, 1.0f / fmaxf(sqrtf(ss1), 1e-12f), d1, lane);
}

// prep roles:
//  [0, NB_W):    w normalize, 2 rows/warp (16 rows/block)
//  [NB_W, +NB_X): x normalize, 2 rows/warp
//  [.., +NB_G):  wm/wk gather+normalize+apm, 1 row/warp
//  last NB_ZERO: zero accumulators (+ first zero block: g_acc/g_ticket)
#define NB_W (CPAD / 16)            // 632
#define NB_X (B_ / 16)              // 128
#define NB_G (B_ / 8)               // 256
#define NB_ZERO 8
#define PREP_XB NB_W
#define PREP_GB (NB_W + NB_X)
#define PREP_ZB (NB_W + NB_X + NB_G)
#define PREP_GRID (PREP_ZB + NB_ZERO)   // 1024

__global__ void __launch_bounds__(256)
prep_kernel(const float* __restrict__ x, const float* __restrict__ w,
            const float* __restrict__ wm, const float* __restrict__ wk,
            const int* __restrict__ label) {
    int b = blockIdx.x, t = threadIdx.x;
    int wv = t >> 5, lane = t & 31;
    if (b < PREP_XB) {
        int r0 = b * 16 + wv * 2;           // w rows r0, r0+1
        if (r0 + 1 < C_) {
            warp_norm2(w + (size_t)r0 * D_, w + (size_t)(r0 + 1) * D_,
                       g_wh + (size_t)r0 * D_, g_wh + (size_t)(r0 + 1) * D_, lane);
        } else {
#pragma unroll
            for (int rr = 0; rr < 2; rr++) {
                int row = r0 + rr;
                __nv_bfloat16* dst = g_wh + (size_t)row * D_;
                if (row >= C_) {
                    uint4* dp = (uint4*)(dst + lane * 16);
                    uint4 z = make_uint4(0u, 0u, 0u, 0u);
                    dp[0] = z; dp[1] = z;
                } else {
                    warp_norm(w + (size_t)row * D_, dst, lane);
                }
            }
        }
    } else if (b < PREP_GB) {
        int r0 = (b - PREP_XB) * 16 + wv * 2;
        warp_norm2(x + (size_t)r0 * D_, x + (size_t)(r0 + 1) * D_,
                   g_xh + (size_t)r0 * D_, g_xh + (size_t)(r0 + 1) * D_, lane);
    } else if (b < PREP_ZB) {
        // gather + normalize wm/wk + apm (ap_m == ap exactly) in one pass
        int i = (b - PREP_GB) * 8 + wv;
        int c = label[i];
        const float4* xp = (const float4*)(x  + (size_t)i * D_) + lane * 4;
        const float4* qp = (const float4*)(wm + (size_t)c * D_) + lane * 4;
        const float4* kp = (const float4*)(wk + (size_t)c * D_) + lane * 4;
        float4 qv[4], kv[4];
        float xx = 0.f, xq = 0.f, qq = 0.f, xk = 0.f, kk = 0.f;
#pragma unroll
        for (int e = 0; e < 4; e++) {
            float4 xv = xp[e];
            qv[e] = qp[e];
            kv[e] = kp[e];
            xx += xv.x * xv.x + xv.y * xv.y + xv.z * xv.z + xv.w * xv.w;
            xq += xv.x * qv[e].x + xv.y * qv[e].y + xv.z * qv[e].z + xv.w * qv[e].w;
            qq += qv[e].x * qv[e].x + qv[e].y * qv[e].y + qv[e].z * qv[e].z + qv[e].w * qv[e].w;
            xk += xv.x * kv[e].x + xv.y * kv[e].y + xv.z * kv[e].z + xv.w * kv[e].w;
            kk += kv[e].x * kv[e].x + kv[e].y * kv[e].y + kv[e].z * kv[e].z + kv[e].w * kv[e].w;
        }
#pragma unroll
        for (int o = 16; o; o >>= 1) {
            xx += __shfl_xor_sync(0xffffffffu, xx, o);
            xq += __shfl_xor_sync(0xffffffffu, xq, o);
            qq += __shfl_xor_sync(0xffffffffu, qq, o);
            xk += __shfl_xor_sync(0xffffffffu, xk, o);
            kk += __shfl_xor_sync(0xffffffffu, kk, o);
        }
        write_norm_bf16(qv, 1.0f / fmaxf(sqrtf(qq), 1e-12f), g_wmh + (size_t)i * D_, lane);
        write_norm_bf16(kv, 1.0f / fmaxf(sqrtf(kk), 1e-12f), g_wkh + (size_t)i * D_, lane);
        if (lane == 0) {
            float dq = xq / fmaxf(sqrtf(xx * qq), 1e-24f);
            float dk = xk / fmaxf(sqrtf(xx * kk), 1e-24f);
            float ap = dq * dk;                 // == ap_m exactly
            float ca = fminf(fmaxf(ap, 0.f), 1.f);
            float sa = sqrt_approx(fminf(fmaxf(1.f - ca, 0.f), 1.f));
            g_cos_apm[i] = ca;
            g_sin_apm[i] = sa;
            float pc = ca * ca - sa * sa;       // cos_ap == cos_apm
            float ps = sqrt_approx(fminf(fmaxf(1.f - pc, 0.f), 1.f));
            float phi_pm = pc * K_COSM - ps * K_SINM;
            g_expneg[i] = exp_approx(1.f - phi_pm);
        }
    } else {
        int idx = (b - PREP_ZB) * 256 + t;
        g_rexp[idx] = 0.f;
        g_rsum[idx] = 0.f;
        g_nmp[idx]  = 0.f;
        if (b == PREP_ZB) {
            if (t < 3) g_acc[t] = 0.f;
            if (t == 3) g_ticket = 0u;
        }
    }
}

// ============== mma.sync bf16 building blocks (R12 proven config) ==============
__device__ __forceinline__ void ldsm4(uint32_t& r0, uint32_t& r1, uint32_t& r2, uint32_t& r3,
                                      uint32_t addr) {
    asm volatile("ldmatrix.sync.aligned.m8n8.x4.shared.b16 {%0,%1,%2,%3},[%4];\n"
                 : "=r"(r0), "=r"(r1), "=r"(r2), "=r"(r3) : "r"(addr));
}
__device__ __forceinline__ void mma16816(float* c, const uint32_t* a, uint32_t b0, uint32_t b1) {
    asm volatile("mma.sync.aligned.m16n8k16.row.col.f32.bf16.bf16.f32 "
                 "{%0,%1,%2,%3},{%4,%5,%6,%7},{%8,%9},{%0,%1,%2,%3};\n"
                 : "+f"(c[0]), "+f"(c[1]), "+f"(c[2]), "+f"(c[3])
                 : "r"(a[0]), "r"(a[1]), "r"(a[2]), "r"(a[3]), "r"(b0), "r"(b1));
}
__device__ __forceinline__ void cpasync16(uint32_t s, const void* g) {
    asm volatile("cp.async.cg.shared.global [%0],[%1],16;\n" :: "r"(s), "l"(g));
}

#define ROWB 80
#define HALFB (128 * ROWB)
#define STAGEB (256 * ROWB)         // 20480 B
#define NSTAGE 4
#define GEMM_SMEM (NSTAGE * STAGEB) // 81920 B
#define NIT_ 16
#define WAITS(it) do {                                                     \
    if ((it) <= NIT_ - 3)      asm volatile("cp.async.wait_group 2;\n");   \
    else if ((it) == NIT_ - 2) asm volatile("cp.async.wait_group 1;\n");   \
    else                       asm volatile("cp.async.wait_group 0;\n");   \
} while (0)

// ---------------- AAM role (128x128 tile) ----------------
struct TileCtx {
    uint32_t aOff[2], bOff[4];
    uint32_t sa0, sa1, sb0, sb1;
    const __nv_bfloat16 *pa0, *pa1, *pb0, *pb1;
    int wm, wn, lane;
};

__device__ __forceinline__ void tile_init(TileCtx& T, uint32_t sbase, int tid,
                                          const __nv_bfloat16* A, const __nv_bfloat16* Bm,
                                          int bm, int bn) {
    int lane = tid & 31, warp = tid >> 5;
    T.lane = lane;
    T.wm = warp >> 1; T.wn = warp & 1;
    uint32_t sA0 = sbase, sB0 = sbase + HALFB;
    int aRow = T.wm * 32 + (lane & 7) + ((lane >> 3) & 1) * 8;
    int aCol = ((lane >> 4) & 1) * 16;
    int bRow = T.wn * 64 + (lane & 7) + ((lane >> 4) & 1) * 8;
    int bCol = ((lane >> 3) & 1) * 16;
#pragma unroll
    for (int mi = 0; mi < 2; mi++) T.aOff[mi] = sA0 + (uint32_t)((aRow + mi * 16) * ROWB + aCol);
#pragma unroll
    for (int nn = 0; nn < 4; nn++) T.bOff[nn] = sB0 + (uint32_t)((bRow + nn * 16) * ROWB + bCol);
    int c0r = tid >> 2, c0k = tid & 3;
    T.sa0 = sA0 + c0r * ROWB + c0k * 16;
    T.sa1 = sA0 + (c0r + 64) * ROWB + c0k * 16;
    T.sb0 = sB0 + c0r * ROWB + c0k * 16;
    T.sb1 = sB0 + (c0r + 64) * ROWB + c0k * 16;
    T.pa0 = A + (size_t)(bm + c0r) * D_ + c0k * 8;
    T.pa1 = A + (size_t)(bm + c0r + 64) * D_ + c0k * 8;
    T.pb0 = Bm + (size_t)(bn + c0r) * D_ + c0k * 8;
    T.pb1 = Bm + (size_t)(bn + c0r + 64) * D_ + c0k * 8;
}

__device__ __forceinline__ void tile_load(const TileCtx& T, int stage, int k0) {
    uint32_t so = (uint32_t)(stage * STAGEB);
    cpasync16(T.sa0 + so, T.pa0 + k0);
    cpasync16(T.sa1 + so, T.pa1 + k0);
    cpasync16(T.sb0 + so, T.pb0 + k0);
    cpasync16(T.sb1 + so, T.pb1 + k0);
    asm volatile("cp.async.commit_group;\n");
}

__device__ __forceinline__ void tile_compute(const TileCtx& T, int stage, float acc[2][8][4]) {
    uint32_t soff = (uint32_t)(stage * STAGEB);
#pragma unroll
    for (int ks = 0; ks < 2; ks++) {
        uint32_t a[2][4];
        ldsm4(a[0][0], a[0][1], a[0][2], a[0][3], T.aOff[0] + soff + ks * 32);
        ldsm4(a[1][0], a[1][1], a[1][2], a[1][3], T.aOff[1] + soff + ks * 32);
        uint32_t b[8][2];
#pragma unroll
        for (int nn = 0; nn < 4; nn++) {
            uint32_t r0, r1, r2, r3;
            ldsm4(r0, r1, r2, r3, T.bOff[nn] + soff + ks * 32);
            b[2 * nn][0] = r0; b[2 * nn][1] = r1;
            b[2 * nn + 1][0] = r2; b[2 * nn + 1][1] = r3;
        }
#pragma unroll
        for (int mi = 0; mi < 2; mi++)
#pragma unroll
            for (int ni = 0; ni < 8; ni++)
                mma16816(acc[mi][ni], a[mi], b[ni][0], b[ni][1]);
    }
}

// ---------------- QK role (128x64 tile, dual accumulators) ----------------
struct QkCtx {
    uint32_t aOff[2], bqOff[2], bkOff[2];
    uint32_t sa0, sa1, sq, sk;
    const __nv_bfloat16 *pa0, *pa1, *pq, *pk;
    int wm, wn, lane;
};

__device__ __forceinline__ void qk_init(QkCtx& T, uint32_t sbase, int tid,
                                        const __nv_bfloat16* A, const __nv_bfloat16* Bq,
                                        const __nv_bfloat16* Bk, int bm, int bn) {
    int lane = tid & 31, warp = tid >> 5;
    T.lane = lane;
    T.wm = warp >> 1; T.wn = warp & 1;
    uint32_t sA0 = sbase, sQ0 = sbase + HALFB, sK0 = sbase + HALFB + 64 * ROWB;
    int aRow = T.wm * 32 + (lane & 7) + ((lane >> 3) & 1) * 8;
    int aCol = ((lane >> 4) & 1) * 16;
    int bRow = T.wn * 32 + (lane & 7) + ((lane >> 4) & 1) * 8;
    int bCol = ((lane >> 3) & 1) * 16;
#pragma unroll
    for (int mi = 0; mi < 2; mi++) T.aOff[mi] = sA0 + (uint32_t)((aRow + mi * 16) * ROWB + aCol);
#pragma unroll
    for (int nn = 0; nn < 2; nn++) {
        T.bqOff[nn] = sQ0 + (uint32_t)((bRow + nn * 16) * ROWB + bCol);
        T.bkOff[nn] = sK0 + (uint32_t)((bRow + nn * 16) * ROWB + bCol);
    }
    int c0r = tid >> 2, c0k = tid & 3;
    T.sa0 = sA0 + c0r * ROWB + c0k * 16;
    T.sa1 = sA0 + (c0r + 64) * ROWB + c0k * 16;
    T.sq  = sQ0 + c0r * ROWB + c0k * 16;
    T.sk  = sK0 + c0r * ROWB + c0k * 16;
    T.pa0 = A  + (size_t)(bm + c0r) * D_ + c0k * 8;
    T.pa1 = A  + (size_t)(bm + c0r + 64) * D_ + c0k * 8;
    T.pq  = Bq + (size_t)(bn + c0r) * D_ + c0k * 8;
    T.pk  = Bk + (size_t)(bn + c0r) * D_ + c0k * 8;
}

__device__ __forceinline__ void qk_load(const QkCtx& T, int stage, int k0) {
    uint32_t so = (uint32_t)(stage * STAGEB);
    cpasync16(T.sa0 + so, T.pa0 + k0);
    cpasync16(T.sa1 + so, T.pa1 + k0);
    cpasync16(T.sq  + so, T.pq  + k0);
    cpasync16(T.sk  + so, T.pk  + k0);
    asm volatile("cp.async.commit_group;\n");
}

__device__ __forceinline__ void qk_compute(const QkCtx& T, int stage,
                                           float aq[2][4][4], float ak[2][4][4]) {
    uint32_t soff = (uint32_t)(stage * STAGEB);
#pragma unroll
    for (int ks = 0; ks < 2; ks++) {
        uint32_t a[2][4];
        ldsm4(a[0][0], a[0][1], a[0][2], a[0][3], T.aOff[0] + soff + ks * 32);
        ldsm4(a[1][0], a[1][1], a[1][2], a[1][3], T.aOff[1] + soff + ks * 32);
        uint32_t bq[4][2], bk[4][2];
#pragma unroll
        for (int nn = 0; nn < 2; nn++) {
            uint32_t r0, r1, r2, r3;
            ldsm4(r0, r1, r2, r3, T.bqOff[nn] + soff + ks * 32);
            bq[2 * nn][0] = r0; bq[2 * nn][1] = r1;
            bq[2 * nn + 1][0] = r2; bq[2 * nn + 1][1] = r3;
            ldsm4(r0, r1, r2, r3, T.bkOff[nn] + soff + ks * 32);
            bk[2 * nn][0] = r0; bk[2 * nn][1] = r1;
            bk[2 * nn + 1][0] = r2; bk[2 * nn + 1][1] = r3;
        }
#pragma unroll
        for (int mi = 0; mi < 2; mi++)
#pragma unroll
            for (int ni = 0; ni < 4; ni++) {
                mma16816(aq[mi][ni], a[mi], bq[ni][0], bq[ni][1]);
                mma16816(ak[mi][ni], a[mi], bk[ni][0], bk[ni][1]);
            }
    }
}

// ---------- nm term ----------
__device__ __forceinline__ float nm_term(float sim, float capm, float sapm) {
    float ca = fminf(fmaxf(sim, 0.f), 1.f);
    float sa = sqrt_approx(fminf(fmaxf(1.f - ca, 0.f), 1.f));
    float ss = sa * capm + ca * sapm;
    float cc = sqrt_approx(fminf(fmaxf(1.f - ss, 0.f), 1.f));
    return exp_approx(ss * K_COSM - cc * K_SINM);
}

// ============== mega kernel: AAM blocks + QK blocks, atomic row accumulation ==============
__global__ void __launch_bounds__(256, 2)
mega_gemm(const __nv_bfloat16* __restrict__ Axh, const __nv_bfloat16* __restrict__ Bw,
          const __nv_bfloat16* __restrict__ Bwm, const __nv_bfloat16* __restrict__ Bwk,
          const int* __restrict__ label) {
    extern __shared__ __align__(16) char smem[];
    uint32_t sbase = (uint32_t)__cvta_generic_to_shared(smem);
    int tid = threadIdx.x;

    if (blockIdx.x < NAAMBLK) {
        int bx = blockIdx.x % NTC, by = blockIdx.x / NTC;
        int bm = by * 128, bn = bx * 128;
        TileCtx T;
        tile_init(T, sbase, tid, Axh, Bw, bm, bn);
        float acc[2][8][4];
#pragma unroll
        for (int mi = 0; mi < 2; mi++)
#pragma unroll
            for (int ni = 0; ni < 8; ni++)
#pragma unroll
                for (int e = 0; e < 4; e++) acc[mi][ni][e] = 0.f;

        tile_load(T, 0, 0);
        tile_load(T, 1, 32);
        tile_load(T, 2, 64);
#pragma unroll
        for (int it = 0; it < NIT_; it++) {
            WAITS(it);
            __syncthreads();
            tile_compute(T, it & 3, acc);
            if (it + 3 < NIT_) tile_load(T, (it + 3) & 3, (it + 3) * 32);
        }

        int lane = T.lane;
        int colbase = bn + T.wn * 64 + (lane & 3) * 2;
#pragma unroll
        for (int mi = 0; mi < 2; mi++) {
#pragma unroll
            for (int h = 0; h < 2; h++) {
                int row = bm + T.wm * 32 + mi * 16 + (lane >> 2) + h * 8;
                int lab = label[row];
                float se = 0.f, sc = 0.f, cy = 0.f;
#pragma unroll
                for (int ni = 0; ni < 8; ni++) {
                    int col = colbase + ni * 8;
                    float v0 = acc[mi][ni][h * 2 + 0];
                    float v1 = acc[mi][ni][h * 2 + 1];
                    if (col < C_) {
                        sc += v0;
                        se += exp_approx(K_S * (v0 - 1.f));
                        if (col == lab) cy = v0;
                    }
                    if (col + 1 < C_) {
                        sc += v1;
                        se += exp_approx(K_S * (v1 - 1.f));
                        if (col + 1 == lab) cy = v1;
                    }
                }
                se += __shfl_xor_sync(0xffffffffu, se, 1);
                se += __shfl_xor_sync(0xffffffffu, se, 2);
                sc += __shfl_xor_sync(0xffffffffu, sc, 1);
                sc += __shfl_xor_sync(0xffffffffu, sc, 2);
                cy += __shfl_xor_sync(0xffffffffu, cy, 1);
                cy += __shfl_xor_sync(0xffffffffu, cy, 2);
                if ((lane & 3) == 0) {
                    atomicAdd(&g_rexp[row], se);
                    atomicAdd(&g_rsum[row], sc);
                    int cb = bn + T.wn * 64;
                    if (lab >= cb && lab < cb + 64) g_cy[row] = cy;
                }
            }
        }
    } else {
        int idx = blockIdx.x - NAAMBLK;
        int cn = idx % NQCT, rm = idx / NQCT;
        int bm = rm * 128, bn = cn * 64;
        QkCtx T;
        qk_init(T, sbase, tid, Axh, Bwm, Bwk, bm, bn);
        float aq[2][4][4], ak[2][4][4];
#pragma unroll
        for (int mi = 0; mi < 2; mi++)
#pragma unroll
            for (int ni = 0; ni < 4; ni++)
#pragma unroll
                for (int e = 0; e < 4; e++) { aq[mi][ni][e] = 0.f; ak[mi][ni][e] = 0.f; }

        qk_load(T, 0, 0);
        qk_load(T, 1, 32);
        qk_load(T, 2, 64);
#pragma unroll
        for (int it = 0; it < NIT_; it++) {
            WAITS(it);
            __syncthreads();
            qk_compute(T, it & 3, aq, ak);
            if (it + 3 < NIT_) qk_load(T, (it + 3) & 3, (it + 3) * 32);
        }

        __syncthreads();
        float* s_capm = (float*)smem;
        float* s_sapm = s_capm + 64;
        int*   s_lcol = (int*)(s_sapm + 64);
        int*   s_lrow = s_lcol + 64;
        if (tid < 64) {
            s_capm[tid] = g_cos_apm[bn + tid];
            s_sapm[tid] = g_sin_apm[bn + tid];
            s_lcol[tid] = label[bn + tid];
        } else if (tid < 192) {
            s_lrow[tid - 64] = label[bm + tid - 64];
        }
        __syncthreads();

        int lane = T.lane;
        int colloc0 = T.wn * 32 + (lane & 3) * 2;
#pragma unroll
        for (int mi = 0; mi < 2; mi++) {
#pragma unroll
            for (int h = 0; h < 2; h++) {
                int rloc = T.wm * 32 + mi * 16 + (lane >> 2) + h * 8;
                int row = bm + rloc;
                int lrow = s_lrow[rloc];
                float s = 0.f;
#pragma unroll
                for (int ni = 0; ni < 4; ni++) {
                    int cl = colloc0 + ni * 8;
                    float s0 = aq[mi][ni][h * 2 + 0] * ak[mi][ni][h * 2 + 0];
                    float s1 = aq[mi][ni][h * 2 + 1] * ak[mi][ni][h * 2 + 1];
                    if (s_lcol[cl] != lrow)     s += nm_term(s0, s_capm[cl], s_sapm[cl]);
                    if (s_lcol[cl + 1] != lrow) s += nm_term(s1, s_capm[cl + 1], s_sapm[cl + 1]);
                }
                s += __shfl_xor_sync(0xffffffffu, s, 1);
                s += __shfl_xor_sync(0xffffffffu, s, 2);
                if ((lane & 3) == 0)
                    atomicAdd(&g_nmp[row], s);
            }
        }
    }
}

// ---------- final combine: 8 blocks, row math parallel, last-block finish ----------
__global__ void __launch_bounds__(256)
final_combine(float* __restrict__ out) {
    int j = blockIdx.x * 256 + threadIdx.x;
    float se = g_rexp[j];
    float sc = g_rsum[j];
    float cyv = g_cy[j];
    float sine = sqrt_approx(fminf(fmaxf(1.f - cyv * cyv, 0.f), 1.f));
    float phi = cyv * K_COSM - sine * K_SINM;
    phi = (cyv - K_TH > 0.f) ? phi : (cyv - K_MM);
    float oy = K_S * phi, ocy = K_S * cyv;
    float sout = K_S * sc + (oy - ocy);
    se += exp_approx(oy - K_S) - exp_approx(ocy - K_S);
    float lse = K_S + log_approx(se);
    float sa = (1.f - K_EPS) * (oy - lse) + (K_EPS / C_) * sout - K_EPS * lse;
    float sn = g_expneg[j];
    float sm = g_nmp[j];
    sa = block_sum_all(sa);
    sn = block_sum_all(sn);
    sm = block_sum_all(sm);
    if (threadIdx.x == 0) {
        atomicAdd(&g_acc[0], sa);
        atomicAdd(&g_acc[1], sn);
        atomicAdd(&g_acc[2], sm);
        __threadfence();
        unsigned t = atomicAdd(&g_ticket, 1u);
        if (t == NFINAL - 1) {
            float fsa = g_acc[0], fsn = g_acc[1], fsm = g_acc[2];
            float aam_loss = -fsa / (float)B_;
            float z = logf(fsm) + logf(fsn);
            float cc = fmaxf(z, 0.f) + log1pf(expf(-fabsf(z)));
            out[0] = aam_loss + cc;
        }
    }
}

// ---------- launcher: 3 launches ----------
extern "C" void kernel_launch(void* const* d_in, const int* in_sizes, int n_in,
                              void* d_out, int out_size) {
    const float* x        = (const float*)d_in[0];
    const int*   label    = (const int*)d_in[1];
    const float* weight   = (const float*)d_in[2];
    const float* weight_m = (const float*)d_in[3];
    const float* weight_n = (const float*)d_in[4];
    float* out = (float*)d_out;

    __nv_bfloat16 *p_xh, *p_wh, *p_wmh, *p_wkh;
    cudaGetSymbolAddress((void**)&p_xh,  g_xh);
    cudaGetSymbolAddress((void**)&p_wh,  g_wh);
    cudaGetSymbolAddress((void**)&p_wmh, g_wmh);
    cudaGetSymbolAddress((void**)&p_wkh, g_wkh);

    cudaFuncSetAttribute(mega_gemm, cudaFuncAttributeMaxDynamicSharedMemorySize, GEMM_SMEM);

    prep_kernel<<<PREP_GRID, 256>>>(x, weight, weight_m, weight_n, label);
    mega_gemm<<<NMEGA, 256, GEMM_SMEM>>>(p_xh, p_wh, p_wmh, p_wkh, label);
    final_combine<<<NFINAL, 256>>>(out);
}